// round 7
// baseline (speedup 1.0000x reference)
#include <cuda_runtime.h>
#include <cuda_bf16.h>
#include <cstdint>

// Problem constants
#define BB 3
#define HH 256
#define WW 256
#define CC 16
#define NB 4
#define COUT 64
#define SN 64
#define EPS 1e-3f

// Scratch (__device__ globals: allocation-free rule)
__device__ float g_x1[BB * HH * WW * COUT];      // conv1 output (BN+ReLU, fp32)
__device__ float g_bf[BB * HH * WW * COUT];      // conv2 out (+softmax+mask fused)
__device__ float g_ratio[BB * SN * SN * CC * NB];
__device__ float g_B1[9 * 64 * 16];              // W1 transposed [t][oc][ic], tf32-rounded
__device__ float g_B2[9 * 64 * 64];              // W2 transposed [t][oc][ic], tf32-rounded

__device__ __forceinline__ uint32_t f2tf32(float f) {
    uint32_t r; asm("cvt.rna.tf32.f32 %0, %1;" : "=r"(r) : "f"(f)); return r;
}

__device__ __forceinline__ void mma_tf32(float& c0, float& c1, float& c2, float& c3,
                                         uint32_t a0, uint32_t a1, uint32_t a2, uint32_t a3,
                                         uint32_t b0, uint32_t b1) {
    asm volatile(
        "mma.sync.aligned.m16n8k8.row.col.f32.tf32.tf32.f32 "
        "{%0,%1,%2,%3}, {%4,%5,%6,%7}, {%8,%9}, {%0,%1,%2,%3};\n"
        : "+f"(c0), "+f"(c1), "+f"(c2), "+f"(c3)
        : "r"(a0), "r"(a1), "r"(a2), "r"(a3), "r"(b0), "r"(b1));
}

// ---------------------------------------------------------------------------
// Weight prep: W [3,3,CIN,64] (HWIO) -> B [9][64][CIN] tf32-rounded fp32
// ---------------------------------------------------------------------------
__global__ void wprep_kernel(const float* __restrict__ W1, const float* __restrict__ W2,
                             float* __restrict__ B1, float* __restrict__ B2)
{
    int i = blockIdx.x * blockDim.x + threadIdx.x;
    if (i < 9 * 64 * 16) {
        int ic = i & 15, oc = (i >> 4) & 63, t = i >> 10;
        uint32_t v = f2tf32(W1[(t * 16 + ic) * 64 + oc]);
        B1[(t * 64 + oc) * 16 + ic] = __uint_as_float(v);
    }
    if (i < 9 * 64 * 64) {
        int ic = i & 63, oc = (i >> 6) & 63, t = i >> 12;
        uint32_t v = f2tf32(W2[(t * 64 + ic) * 64 + oc]);
        B2[(t * 64 + oc) * 64 + ic] = __uint_as_float(v);
    }
}

// ---------------------------------------------------------------------------
// Implicit-GEMM 3x3 SAME conv via mma.sync tf32 + folded BN.
// CTA = one image row: 256 px x 64 oc; 8 warps, warp tile M=32 x N=64.
// Double-buffered (ky, 16-ic chunk) stages: LDG(s+1) -> MMA(s) -> STS(s+1)
// -> one __syncthreads per stage. kx taps = +kx row offset into A tile.
// Epilogue: BN (+ReLU for conv1, +softmax/mask over NB=4 via lane^1 shfl
// for conv2).
// ---------------------------------------------------------------------------
#define ASTR 20
#define A_FLOATS (258 * ASTR)
#define B_FLOATS (3 * 64 * ASTR)
#define CONV_SMEM ((2 * A_FLOATS + 2 * B_FLOATS) * 4)

template <int CIN, int DO_RELU, int DO_SOFTMAX>
__global__ __launch_bounds__(256) void conv_mma(
    const float* __restrict__ in, const float* __restrict__ Bw,
    const float* __restrict__ bias, const float* __restrict__ gam,
    const float* __restrict__ bet, const float* __restrict__ mu,
    const float* __restrict__ var, float* __restrict__ out)
{
    constexpr int NCH = CIN / 16;
    constexpr int NSTAGE = 3 * NCH;

    extern __shared__ __align__(16) float dynsm[];
    float* s_a[2] = { dynsm, dynsm + A_FLOATS };
    float* s_b[2] = { dynsm + 2 * A_FLOATS, dynsm + 2 * A_FLOATS + B_FLOATS };
    __shared__ float s_sc[64], s_sh[64];

    const int tid  = threadIdx.x;
    const int lane = tid & 31;
    const int warp = tid >> 5;     // 0..7
    const int lg   = lane >> 2;
    const int lt   = lane & 3;
    const int wp0  = warp * 32;    // warp pixel base

    const int y  = blockIdx.x;
    const int bb = blockIdx.y;

    if (tid < 64) {
        float sc = gam[tid] * rsqrtf(var[tid] + EPS);
        s_sc[tid] = sc;
        s_sh[tid] = (bias[tid] - mu[tid]) * sc + bet[tid];
    }

    float acc[2][8][4];
#pragma unroll
    for (int mt = 0; mt < 2; ++mt)
#pragma unroll
        for (int n = 0; n < 8; ++n)
#pragma unroll
            for (int c = 0; c < 4; ++c) acc[mt][n][c] = 0.f;

    float4 apf[5];      // A prefetch (1032 float4 / 256 thr)
    float4 bpf[3];      // B prefetch (768 float4 / 256 thr)

    auto LOAD = [&](int s) {
        const int ky  = s / NCH;
        const int ic0 = (s % NCH) * 16;
        const int gy  = y + ky - 1;
        const bool rok = (unsigned)gy < (unsigned)HH;
        const float* rowp = in + ((size_t)(bb * HH + gy) * WW) * CIN + ic0;
#pragma unroll
        for (int k = 0; k < 5; ++k) {
            int idx = tid + k * 256;
            apf[k] = make_float4(0.f, 0.f, 0.f, 0.f);
            if (idx < 1032) {
                int c4 = idx & 3, p = idx >> 2, gx = p - 1;
                if (rok && (unsigned)gx < (unsigned)WW)
                    apf[k] = *(const float4*)(rowp + gx * CIN + c4 * 4);
            }
        }
#pragma unroll
        for (int k = 0; k < 3; ++k) {
            int idx = tid + k * 256;
            int c4 = idx & 3, oc = (idx >> 2) & 63, tap = idx >> 8;
            bpf[k] = *(const float4*)(Bw + ((ky * 3 + tap) * 64 + oc) * CIN + ic0 + c4 * 4);
        }
    };

    auto STORE = [&](int b) {
#pragma unroll
        for (int k = 0; k < 5; ++k) {
            int idx = tid + k * 256;
            if (idx < 1032) {
                int c4 = idx & 3, p = idx >> 2;
                uint4 v;
                v.x = f2tf32(apf[k].x); v.y = f2tf32(apf[k].y);
                v.z = f2tf32(apf[k].z); v.w = f2tf32(apf[k].w);
                *(uint4*)&s_a[b][p * ASTR + c4 * 4] = v;
            }
        }
#pragma unroll
        for (int k = 0; k < 3; ++k) {
            int idx = tid + k * 256;
            int c4 = idx & 3, oc = (idx >> 2) & 63, tap = idx >> 8;
            *(float4*)&s_b[b][(tap * 64 + oc) * ASTR + c4 * 4] = bpf[k];
        }
    };

    auto MMAS = [&](int b) {
#pragma unroll
        for (int kx = 0; kx < 3; ++kx) {
#pragma unroll
            for (int g = 0; g < 2; ++g) {
                const int icw = g * 8 + lt;
                uint32_t b0[8], b1[8];
#pragma unroll
                for (int n = 0; n < 8; ++n) {
                    const float* bp = &s_b[b][(kx * 64 + n * 8 + lg) * ASTR + icw];
                    b0[n] = __float_as_uint(bp[0]);
                    b1[n] = __float_as_uint(bp[4]);
                }
#pragma unroll
                for (int mt = 0; mt < 2; ++mt) {
                    const int r0 = wp0 + mt * 16 + kx + lg;
                    const float* ap = &s_a[b][r0 * ASTR + icw];
                    uint32_t a0 = __float_as_uint(ap[0]);
                    uint32_t a1 = __float_as_uint(ap[8 * ASTR]);
                    uint32_t a2 = __float_as_uint(ap[4]);
                    uint32_t a3 = __float_as_uint(ap[8 * ASTR + 4]);
#pragma unroll
                    for (int n = 0; n < 8; ++n)
                        mma_tf32(acc[mt][n][0], acc[mt][n][1], acc[mt][n][2], acc[mt][n][3],
                                 a0, a1, a2, a3, b0[n], b1[n]);
                }
            }
        }
    };

    // pipeline
    LOAD(0); STORE(0);
    __syncthreads();
    for (int s = 0; s < NSTAGE; ++s) {
        if (s + 1 < NSTAGE) LOAD(s + 1);
        MMAS(s & 1);
        if (s + 1 < NSTAGE) STORE((s + 1) & 1);
        __syncthreads();
    }

    // ---- epilogue
    float* ob = out + ((size_t)(bb * HH + y) * WW) * COUT;
#pragma unroll
    for (int mt = 0; mt < 2; ++mt) {
        int prow = wp0 + mt * 16 + lg;
#pragma unroll
        for (int n = 0; n < 8; ++n) {
            int col = n * 8 + lt * 2;
            float sc0 = s_sc[col], sc1 = s_sc[col + 1];
            float sh0 = s_sh[col], sh1 = s_sh[col + 1];
            float v0 = acc[mt][n][0] * sc0 + sh0;
            float v1 = acc[mt][n][1] * sc1 + sh1;
            float v2 = acc[mt][n][2] * sc0 + sh0;
            float v3 = acc[mt][n][3] * sc1 + sh1;
            if (DO_RELU) {
                v0 = fmaxf(v0, 0.f); v1 = fmaxf(v1, 0.f);
                v2 = fmaxf(v2, 0.f); v3 = fmaxf(v3, 0.f);
            }
            if (DO_SOFTMAX) {
                // NB=4 group spans lane pair (lane ^ 1): two shfl-xor reductions
                // rows lg (v0,v1)
                float m01 = fmaxf(v0, v1);
                m01 = fmaxf(m01, __shfl_xor_sync(0xffffffffu, m01, 1));
                float e0 = __expf(v0 - m01), e1 = __expf(v1 - m01);
                float s01 = e0 + e1;
                s01 += __shfl_xor_sync(0xffffffffu, s01, 1);
                float inv01 = 1.f / s01;
                v0 = e0 * inv01; v1 = e1 * inv01;
                v0 = v0 > 1e-5f ? v0 : 0.f;
                v1 = v1 > 1e-5f ? v1 : 0.f;
                // rows lg+8 (v2,v3)
                float m23 = fmaxf(v2, v3);
                m23 = fmaxf(m23, __shfl_xor_sync(0xffffffffu, m23, 1));
                float e2 = __expf(v2 - m23), e3 = __expf(v3 - m23);
                float s23 = e2 + e3;
                s23 += __shfl_xor_sync(0xffffffffu, s23, 1);
                float inv23 = 1.f / s23;
                v2 = e2 * inv23; v3 = e3 * inv23;
                v2 = v2 > 1e-5f ? v2 : 0.f;
                v3 = v3 > 1e-5f ? v3 : 0.f;
            }
            *(float2*)(ob + (size_t)prow * COUT + col)       = make_float2(v0, v1);
            *(float2*)(ob + (size_t)(prow + 8) * COUT + col) = make_float2(v2, v3);
        }
    }
}

// ---------------------------------------------------------------------------
// Per-patch ratio = divide_no_nan(sum(pet*b), sum(b)) per (cc, f).
// ---------------------------------------------------------------------------
__global__ __launch_bounds__(256) void ratio_kernel(
    const float* __restrict__ bf, const float* __restrict__ pet,
    float* __restrict__ ratio)
{
    int tid = threadIdx.x;
    int pid = blockIdx.x * 16 + (tid >> 4);
    int cc  = tid & 15;
    int b   = pid >> 12;
    int nm  = pid & 4095;
    int n   = nm >> 6;
    int m   = nm & 63;

    float4 dn = make_float4(0.f, 0.f, 0.f, 0.f);
    float4 kp = make_float4(0.f, 0.f, 0.f, 0.f);
    int gx0 = n * 4 - 2, gy0 = m * 4 - 2;

    for (int xp = 0; xp < 8; ++xp) {
        int gx = gx0 + xp;
        if ((unsigned)gx >= (unsigned)HH) continue;
        for (int yp = 0; yp < 8; ++yp) {
            int gy = gy0 + yp;
            if ((unsigned)gy >= (unsigned)WW) continue;
            int pix = (b * HH + gx) * WW + gy;
            float4 bv = *(const float4*)&bf[pix * COUT + cc * 4];
            float  pv = pet[pix * CC + cc];
            dn.x += bv.x; dn.y += bv.y; dn.z += bv.z; dn.w += bv.w;
            kp.x = fmaf(pv, bv.x, kp.x);
            kp.y = fmaf(pv, bv.y, kp.y);
            kp.z = fmaf(pv, bv.z, kp.z);
            kp.w = fmaf(pv, bv.w, kp.w);
        }
    }
    float4 r;
    r.x = dn.x != 0.f ? kp.x / dn.x : 0.f;
    r.y = dn.y != 0.f ? kp.y / dn.y : 0.f;
    r.z = dn.z != 0.f ? kp.z / dn.z : 0.f;
    r.w = dn.w != 0.f ? kp.w / dn.w : 0.f;
    ((float4*)ratio)[pid * 16 + cc] = r;
}

// ---------------------------------------------------------------------------
// Final gather: deinterleave + roll + mean collapsed form.
// ---------------------------------------------------------------------------
__global__ void out_kernel(const float* __restrict__ bf,
                           const float* __restrict__ ratio,
                           float* __restrict__ out, int ntot)
{
    int idx = blockIdx.x * blockDim.x + threadIdx.x;
    if (idx >= ntot) return;
    int cc  = idx & 15;
    int pix = idx >> 4;
    int Y = pix & 255;
    int t = pix >> 8;
    int X = t & 255;
    int b = t >> 8;

    float s = 0.f;
#pragma unroll
    for (int j = 0; j < 2; ++j) {
        int Yp = (Y - (j ? 2 : -2)) & 255;
        int m  = (Yp >> 3) * 2 + j;
        int gy = Yp + 4 * j - 2;
#pragma unroll
        for (int i = 0; i < 2; ++i) {
            int Xp = (X - (i ? 2 : -2)) & 255;
            int n  = (Xp >> 3) * 2 + i;
            int gx = Xp + 4 * i - 2;
            if ((unsigned)gx < (unsigned)HH && (unsigned)gy < (unsigned)WW) {
                int pp = (b * HH + gx) * WW + gy;
                float4 bv = *(const float4*)&bf[pp * COUT + cc * 4];
                float4 rv = *(const float4*)&ratio[(((b * SN + n) * SN + m) * CC + cc) * 4];
                s += bv.x * rv.x + bv.y * rv.y + bv.z * rv.z + bv.w * rv.w;
            }
        }
    }
    out[idx] = s * 0.25f;
}

// ---------------------------------------------------------------------------
extern "C" void kernel_launch(void* const* d_in, const int* in_sizes, int n_in,
                              void* d_out, int out_size)
{
    const float* mr  = (const float*)d_in[0];
    const float* pet = (const float*)d_in[1];
    const float* W1  = (const float*)d_in[2];
    const float* b1  = (const float*)d_in[3];
    const float* g1  = (const float*)d_in[4];
    const float* be1 = (const float*)d_in[5];
    const float* mu1 = (const float*)d_in[6];
    const float* v1  = (const float*)d_in[7];
    const float* W2  = (const float*)d_in[8];
    const float* b2  = (const float*)d_in[9];
    const float* g2  = (const float*)d_in[10];
    const float* be2 = (const float*)d_in[11];
    const float* mu2 = (const float*)d_in[12];
    const float* v2  = (const float*)d_in[13];
    float* outp = (float*)d_out;

    float *x1p, *bfp, *ratp, *B1p, *B2p;
    cudaGetSymbolAddress((void**)&x1p, g_x1);
    cudaGetSymbolAddress((void**)&bfp, g_bf);
    cudaGetSymbolAddress((void**)&ratp, g_ratio);
    cudaGetSymbolAddress((void**)&B1p, g_B1);
    cudaGetSymbolAddress((void**)&B2p, g_B2);

    static int configured = 0;
    if (!configured) {
        cudaFuncSetAttribute(conv_mma<16, 1, 0>, cudaFuncAttributeMaxDynamicSharedMemorySize, CONV_SMEM);
        cudaFuncSetAttribute(conv_mma<64, 0, 1>, cudaFuncAttributeMaxDynamicSharedMemorySize, CONV_SMEM);
        configured = 1;
    }

    wprep_kernel<<<(9 * 64 * 64 + 255) / 256, 256>>>(W1, W2, B1p, B2p);

    dim3 cgrid(HH, BB);
    conv_mma<16, 1, 0><<<cgrid, 256, CONV_SMEM>>>(mr, B1p, b1, g1, be1, mu1, v1, x1p);
    conv_mma<64, 0, 1><<<cgrid, 256, CONV_SMEM>>>(x1p, B2p, b2, g2, be2, mu2, v2, bfp);

    ratio_kernel<<<(BB * SN * SN) / 16, 256>>>(bfp, pet, ratp);

    int ntot = BB * HH * WW * CC;
    out_kernel<<<(ntot + 255) / 256, 256>>>(bfp, ratp, outp, ntot);
}